// round 11
// baseline (speedup 1.0000x reference)
#include <cuda_runtime.h>
#include <cuda_bf16.h>

#define NX 1024
#define NY 1024
#define EPSV 1e-10f

// Per-cell interpolation params: (x_i, x_{i+1}, 1/dx, pad). Cell i covers [g[i], g[i+1]).
__device__ float4 g_cell_x[NX];
__device__ float4 g_cell_y[NY];

// Quad table: u_quad[i*NY + j] = (u[i][j], u[i][j+1], u[i+1][j], u[i+1][j+1])
__device__ float4 g_u_quad[NX * NY];

// ---------------------------------------------------------------------------
// Kernel 1: build adaptive grids + per-cell params. One block per axis.
// Warp-shuffle double scan: 2 barriers instead of 20.
// ---------------------------------------------------------------------------
__global__ __launch_bounds__(1024) void build_grids_kernel(
    const float* __restrict__ inc_x,
    const float* __restrict__ inc_y)
{
    const int axis = blockIdx.x;
    const float* inc = (axis == 0) ? inc_x : inc_y;
    float4* cell     = (axis == 0) ? g_cell_x : g_cell_y;
    const int n      = (axis == 0) ? NX : NY;

    __shared__ double warp_sum[32];
    __shared__ float  sg[1024];
    const int t    = threadIdx.x;
    const int lane = t & 31;
    const int wid  = t >> 5;

    double v = 0.0;
    if (t < n - 1) {
        float x  = inc[t];
        float sp = fmaxf(x, 0.0f) + log1pf(expf(-fabsf(x)));  // stable softplus
        sp = fmaxf(sp, 1e-6f);
        v = (double)sp;
    }

    // warp-level inclusive scan (double)
    double x = v;
    #pragma unroll
    for (int off = 1; off < 32; off <<= 1) {
        double y = __shfl_up_sync(0xFFFFFFFFu, x, off);
        if (lane >= off) x += y;
    }
    if (lane == 31) warp_sum[wid] = x;
    __syncthreads();

    if (wid == 0) {
        double w = warp_sum[lane];
        #pragma unroll
        for (int off = 1; off < 32; off <<= 1) {
            double y = __shfl_up_sync(0xFFFFFFFFu, w, off);
            if (lane >= off) w += y;
        }
        warp_sum[lane] = w;
    }
    __syncthreads();

    const double offset = (wid > 0) ? warp_sum[wid - 1] : 0.0;
    const double cum    = x + offset;
    const double total  = warp_sum[31];   // == cum at index n-2 (tail slots add 0)

    if (t == 0) sg[0] = 0.0f;
    if (t < n - 1) {
        float val = (float)(cum / total);
        if (t == n - 2) val = 1.0f;       // pinned endpoint
        sg[t + 1] = val;
    }
    __syncthreads();

    if (t < n - 1) {
        float x0 = sg[t], x1 = sg[t + 1];
        float dx = fmaxf(x1 - x0, EPSV);
        cell[t] = make_float4(x0, x1, __frcp_rn(dx), 0.0f);
    } else {
        cell[t] = make_float4(1.0f, 1.0f, 0.0f, 0.0f);
    }
}

// ---------------------------------------------------------------------------
// Kernel 2: build quad table. Coalesced columns, one row per blockIdx.y.
// ---------------------------------------------------------------------------
__global__ __launch_bounds__(256) void build_uquad_kernel(const float* __restrict__ u)
{
    const int j = blockIdx.x * blockDim.x + threadIdx.x;
    const int i = blockIdx.y;
    if (i >= NX - 1 || j >= NY - 1) return;

    const float* r0 = u + (size_t)i * NY + j;
    g_u_quad[(size_t)i * NY + j] =
        make_float4(__ldg(r0), __ldg(r0 + 1), __ldg(r0 + NY), __ldg(r0 + NY + 1));
}

// ---------------------------------------------------------------------------
// Kernel 3: bilinear interpolation, 8 points/thread for MLP.
// ---------------------------------------------------------------------------
struct AxisHit { int idx; float n1, n2; };

__device__ __forceinline__ AxisHit locate(const float4* __restrict__ cells, float v)
{
    int i = (int)(v * 1023.0f);
    i = max(0, min(i, 1022));
    float4 c = cells[i];
    int adj = (v >= c.y ? 1 : 0) - (v < c.x ? 1 : 0);
    if (adj != 0) {                       // rare: guess off by one
        i = max(0, min(i + adj, 1022));
        c = cells[i];
    }
    AxisHit h;
    h.idx = i;
    h.n1 = (c.y - v) * c.z;
    h.n2 = (v - c.x) * c.z;
    return h;
}

#define PTS 8

__global__ __launch_bounds__(256) void interp_kernel(
    const float* __restrict__ x_eval,   // [n, 2] interleaved
    float* __restrict__ out,            // [n]
    int n)
{
    __shared__ float4 cx[NX];
    __shared__ float4 cy[NY];
    for (int i = threadIdx.x; i < NX; i += blockDim.x) cx[i] = g_cell_x[i];
    for (int i = threadIdx.x; i < NY; i += blockDim.x) cy[i] = g_cell_y[i];
    __syncthreads();

    const int base = (blockIdx.x * blockDim.x + threadIdx.x) * PTS;
    if (base >= n) return;

    if (base + PTS - 1 < n) {
        // 4 streaming float4 loads = 8 (x,y) pairs
        float4 p[PTS / 2];
        #pragma unroll
        for (int m = 0; m < PTS / 2; m++)
            p[m] = __ldcs(reinterpret_cast<const float4*>(x_eval + 2 * (size_t)base + 4 * m));

        AxisHit hx[PTS], hy[PTS];
        #pragma unroll
        for (int m = 0; m < PTS / 2; m++) {
            hx[2 * m]     = locate(cx, p[m].x);
            hy[2 * m]     = locate(cy, p[m].y);
            hx[2 * m + 1] = locate(cx, p[m].z);
            hy[2 * m + 1] = locate(cy, p[m].w);
        }

        // 8 independent gathers, batched (one LDG.128 each)
        float4 q[PTS];
        #pragma unroll
        for (int k = 0; k < PTS; k++)
            q[k] = __ldg(&g_u_quad[(size_t)hx[k].idx * NY + hy[k].idx]);

        float r[PTS];
        #pragma unroll
        for (int k = 0; k < PTS; k++) {
            r[k] = hx[k].n1 * (hy[k].n1 * q[k].x + hy[k].n2 * q[k].y)
                 + hx[k].n2 * (hy[k].n1 * q[k].z + hy[k].n2 * q[k].w);
        }
        __stcs(reinterpret_cast<float4*>(out + base),
               make_float4(r[0], r[1], r[2], r[3]));
        __stcs(reinterpret_cast<float4*>(out + base + 4),
               make_float4(r[4], r[5], r[6], r[7]));
    } else {
        for (int k = 0; k < PTS && base + k < n; k++) {
            float xe = x_eval[2 * (size_t)(base + k)];
            float ye = x_eval[2 * (size_t)(base + k) + 1];
            AxisHit hx = locate(cx, xe);
            AxisHit hy = locate(cy, ye);
            float4 q = __ldg(&g_u_quad[(size_t)hx.idx * NY + hy.idx]);
            out[base + k] = hx.n1 * (hy.n1 * q.x + hy.n2 * q.y)
                          + hx.n2 * (hy.n1 * q.z + hy.n2 * q.w);
        }
    }
}

// ---------------------------------------------------------------------------
// Launch
// ---------------------------------------------------------------------------
extern "C" void kernel_launch(void* const* d_in, const int* in_sizes, int n_in,
                              void* d_out, int out_size)
{
    const float* x_eval = (const float*)d_in[0];   // [N_EVAL, 2]
    const float* inc_x  = (const float*)d_in[1];   // [NX-1]
    const float* inc_y  = (const float*)d_in[2];   // [NY-1]
    const float* u      = (const float*)d_in[3];   // [NX, NY]
    float* out          = (float*)d_out;

    const int n = out_size;

    build_grids_kernel<<<2, 1024>>>(inc_x, inc_y);

    dim3 qgrid((NY + 255) / 256, NX);
    build_uquad_kernel<<<qgrid, 256>>>(u);

    const int threads = 256;
    const int per_block = threads * PTS;
    const int blocks = (n + per_block - 1) / per_block;
    interp_kernel<<<blocks, threads>>>(x_eval, out, n);
}